// round 4
// baseline (speedup 1.0000x reference)
#include <cuda_runtime.h>
#include <math.h>

// Problem shape (fixed by the dataset): B=8, T=4096, D=64
constexpr int B = 8;
constexpr int T = 4096;
constexpr int D = 64;
constexpr float INV_TEMP = 10.0f;   // 1 / 0.1

// -------- device scratch (no allocations allowed) --------
__device__ float g_Xsel[B][T][D];   // normalized, compacted selected rows of x
__device__ float g_Ysel[B][T][D];   // normalized, compacted selected rows of y
__device__ int   g_rsel[B][T];
__device__ int   g_csel[B][T];
__device__ int   g_nx[B];
__device__ int   g_ny[B];
__device__ float g_percol[B][T];    // per-column loss terms (lse - diag), j < m

// -------- packed f32x2 helpers (FFMA2: 2 MACs per issue slot) --------
__device__ __forceinline__ void fma2(unsigned long long& d,
                                     unsigned long long a,
                                     unsigned long long b) {
    asm("fma.rn.f32x2 %0, %1, %2, %0;" : "+l"(d) : "l"(a), "l"(b));
}
__device__ __forceinline__ void add2(unsigned long long& d,
                                     unsigned long long a,
                                     unsigned long long b) {
    asm("add.rn.f32x2 %0, %1, %2;" : "=l"(d) : "l"(a), "l"(b));
}
__device__ __forceinline__ float hsum2(unsigned long long a) {
    float lo, hi;
    asm("mov.b64 {%0, %1}, %2;" : "=f"(lo), "=f"(hi) : "l"(a));
    return lo + hi;
}

// ============================================================
// Kernel 1: stable compaction of selected indices (per batch)
// 1024 threads, each owns 4 contiguous positions -> stable order
// ============================================================
__global__ void compact_kernel(const int* __restrict__ im1, const int* __restrict__ im2,
                               const int* __restrict__ sh1, const int* __restrict__ sh2) {
    int b   = blockIdx.x;
    int tid = threadIdx.x;
    int lane = tid & 31, wid = tid >> 5;
    __shared__ int wtot[32];

    for (int sel = 0; sel < 2; ++sel) {
        const int* im = sel ? im2 : im1;
        const int* sh = sel ? sh2 : sh1;
        int* outp = sel ? &g_csel[b][0] : &g_rsel[b][0];

        int t0 = tid * 4;
        int v[4];
        int cnt = 0;
        #pragma unroll
        for (int i = 0; i < 4; ++i) {
            int t = t0 + i;
            v[i] = (im[b * T + t] != 0 && sh[b * T + t] != 0) ? 1 : 0;
            cnt += v[i];
        }
        // warp inclusive scan of cnt
        int incl = cnt;
        #pragma unroll
        for (int o = 1; o < 32; o <<= 1) {
            int tt = __shfl_up_sync(0xffffffffu, incl, o);
            if (lane >= o) incl += tt;
        }
        if (lane == 31) wtot[wid] = incl;
        __syncthreads();
        if (wid == 0) {
            int val  = wtot[lane];
            int winc = val;
            #pragma unroll
            for (int o = 1; o < 32; o <<= 1) {
                int tt = __shfl_up_sync(0xffffffffu, winc, o);
                if (lane >= o) winc += tt;
            }
            wtot[lane] = winc - val;              // exclusive warp offsets
            if (lane == 31) {
                if (sel) g_ny[b] = winc; else g_nx[b] = winc;  // total count
            }
        }
        __syncthreads();
        int off = wtot[wid] + (incl - cnt);
        #pragma unroll
        for (int i = 0; i < 4; ++i)
            if (v[i]) outp[off++] = t0 + i;
        __syncthreads();   // smem reuse next iteration
    }
}

// ============================================================
// Kernel 2: gather selected rows + L2-normalize into Xsel/Ysel
// grid: (T/8, B, 2) ; block 256 (8 warps), warp = one row
// ============================================================
__global__ void gather_norm_kernel(const float* __restrict__ x, const float* __restrict__ y) {
    int b     = blockIdx.y;
    int which = blockIdx.z;                 // 0 -> x, 1 -> y
    int wid  = threadIdx.x >> 5;
    int lane = threadIdx.x & 31;
    int p = blockIdx.x * 8 + wid;

    int count = which ? g_ny[b] : g_nx[b];
    if (p >= count) return;
    int r = which ? g_csel[b][p] : g_rsel[b][p];

    const float* src = (which ? y : x) + ((size_t)b * T + r) * D;
    float2 v = reinterpret_cast<const float2*>(src)[lane];
    float ss = v.x * v.x + v.y * v.y;
    #pragma unroll
    for (int o = 16; o > 0; o >>= 1) ss += __shfl_xor_sync(0xffffffffu, ss, o);
    float n  = sqrtf(ss);
    float sc = 1.0f / fmaxf(n, 1e-12f);

    float* dst = which ? &g_Ysel[b][p][0] : &g_Xsel[b][p][0];
    reinterpret_cast<float2*>(dst)[lane] = make_float2(v.x * sc, v.y * sc);
}

// ============================================================
// Kernel 3: fused GEMM + online column-LSE + diagonal capture
// grid: (ceil(T/32), B), block 256.
// Each of 32 lanes owns one column c (y-vector packed f32x2 in 64 regs);
// 8 row-lane warps stream Xsel rows through smem (broadcast LDS.128).
// Inner loop: 16 LDS.128 + 32 FFMA2 per row (2 MACs / issue slot).
// ============================================================
__global__ void __launch_bounds__(256)
simloss_kernel() {
    int b  = blockIdx.y;
    int nx = g_nx[b];
    int ny = g_ny[b];
    int m  = min(nx, ny);
    int colbase = blockIdx.x * 32;
    if (colbase >= m) return;

    int tid  = threadIdx.x;
    int lane = tid & 31;       // column within tile
    int rl   = tid >> 5;       // row-lane (warp id), 0..7
    int c    = colbase + lane; // global selected-column index (c < T always)
    bool cvalid = (c < m);

    // y column, packed as 32 f32x2 (register pairs), loaded via 16B loads
    unsigned long long y2[32];
    {
        const ulonglong2* yp = reinterpret_cast<const ulonglong2*>(&g_Ysel[b][c][0]);
        #pragma unroll
        for (int k = 0; k < 16; ++k) {
            ulonglong2 t = yp[k];
            y2[2 * k]     = t.x;
            y2[2 * k + 1] = t.y;
        }
    }

    __shared__ __align__(16) float xs[32 * D];     // 32-row tile of Xsel (8 KB)
    __shared__ float redM[8][32], redS[8][32], redD[8][32];

    float runM = -3.0e38f;
    float runS = 0.0f;
    float diag = 0.0f;

    for (int rb = 0; rb < nx; rb += 32) {
        __syncthreads();
        // cooperative coalesced load: 32*64 floats = 512 float4 by 256 threads
        {
            const float4* src = reinterpret_cast<const float4*>(&g_Xsel[b][rb][0]);
            float4*       dst = reinterpret_cast<float4*>(xs);
            #pragma unroll
            for (int i = 0; i < 2; ++i)
                dst[tid + i * 256] = src[tid + i * 256];
        }
        __syncthreads();

        #pragma unroll
        for (int rr = 0; rr < 4; ++rr) {
            int rlocal = rl + rr * 8;
            int grow   = rb + rlocal;
            if (grow >= nx) continue;              // warp-uniform branch
            const ulonglong2* xp = reinterpret_cast<const ulonglong2*>(&xs[rlocal * D]);
            unsigned long long acc0 = 0ull;        // two packed fp32 zeros
            unsigned long long acc1 = 0ull;
            #pragma unroll
            for (int k = 0; k < 16; ++k) {
                ulonglong2 t = xp[k];              // broadcast LDS.128 (uniform addr)
                fma2(acc0, t.x, y2[2 * k]);
                fma2(acc1, t.y, y2[2 * k + 1]);
            }
            unsigned long long accp;
            add2(accp, acc0, acc1);
            float s = hsum2(accp) * INV_TEMP;
            if (grow == c) diag = s;               // diagonal element of compacted sim
            // online logsumexp update (1 exp per row typical)
            if (s <= runM) {
                runS += __expf(s - runM);
            } else {
                runS = runS * __expf(runM - s) + 1.0f;
                runM = s;
            }
        }
    }

    // merge the 8 row-lane partials per column
    redM[rl][lane] = runM;
    redS[rl][lane] = runS;
    redD[rl][lane] = diag;
    __syncthreads();
    if (rl == 0 && cvalid) {
        float M = -3.0e38f;
        #pragma unroll
        for (int i = 0; i < 8; ++i) M = fmaxf(M, redM[i][lane]);
        float S = 0.0f, Dg = 0.0f;
        #pragma unroll
        for (int i = 0; i < 8; ++i) {
            S  += redS[i][lane] * __expf(redM[i][lane] - M);
            Dg += redD[i][lane];                   // exactly one nonzero contributor
        }
        float lse = M + logf(S);
        g_percol[b][c] = lse - Dg;
    }
}

// ============================================================
// Kernel 4: deterministic final reduction -> scalar mean loss
// ============================================================
__global__ void final_reduce_kernel(float* __restrict__ out) {
    __shared__ float red[256];
    int tid = threadIdx.x;
    float total = 0.0f;
    for (int b = 0; b < B; ++b) {
        int m = min(g_nx[b], g_ny[b]);
        float s = 0.0f;
        for (int j = tid; j < m; j += 256) s += g_percol[b][j];
        red[tid] = s;
        __syncthreads();
        for (int st = 128; st > 0; st >>= 1) {
            if (tid < st) red[tid] += red[tid + st];
            __syncthreads();
        }
        if (tid == 0 && m > 0) total += red[0] / (float)m;
        __syncthreads();
    }
    if (tid == 0) out[0] = total / (float)B;
}

// ============================================================
extern "C" void kernel_launch(void* const* d_in, const int* in_sizes, int n_in,
                              void* d_out, int out_size) {
    const float* x   = (const float*)d_in[0];
    const float* y   = (const float*)d_in[1];
    const int*   im1 = (const int*)d_in[2];
    const int*   im2 = (const int*)d_in[3];
    const int*   sh1 = (const int*)d_in[4];
    const int*   sh2 = (const int*)d_in[5];

    compact_kernel<<<B, 1024>>>(im1, im2, sh1, sh2);
    gather_norm_kernel<<<dim3(T / 8, B, 2), 256>>>(x, y);
    simloss_kernel<<<dim3(T / 32, B), 256>>>();
    final_reduce_kernel<<<1, 256>>>((float*)d_out);
}